// round 4
// baseline (speedup 1.0000x reference)
#include <cuda_runtime.h>
#include <math.h>

#define Nn 50000
#define Ee 800000
#define HID 64
#define EAD 16
#define NLAY 3
#define NCLS 10
#define NGR 64

// ---------------- static scratch (no allocs allowed) ----------------
__device__ float d_x[(size_t)Nn*HID];          // current node features
__device__ float d_ea[(size_t)Ee*HID];         // encoded edge attrs, CSR-sorted by dst
__device__ int   d_srcs[Ee];                   // src node per sorted edge
__device__ int   d_eperm[Ee];                  // sorted pos -> original edge id
__device__ int   d_degi[Nn];
__device__ int   d_off[Nn+1];
__device__ int   d_cursor[Nn];
__device__ float d_amp[Nn], d_att[Nn];
__device__ float d_avglog;
__device__ float d_agg[(size_t)Nn*768];        // [mean|mn|mx|std] x 192
__device__ float d_y[(size_t)Nn*192];          // GEMM out before amp/att combine
__device__ float d_h[(size_t)Nn*HID];          // pre-BN layer output
__device__ float d_bnsum[HID], d_bnss[HID];
__device__ float d_pool[NGR*HID];
__device__ float d_cntg[NGR];

// ---------------- setup kernels ----------------
__global__ __launch_bounds__(256) void k_zero() {
    int i = blockIdx.x*blockDim.x + threadIdx.x;
    if (i < Nn) { d_degi[i] = 0; d_cursor[i] = 0; }
    if (i < NGR*HID) d_pool[i] = 0.f;
    if (i < NGR) d_cntg[i] = 0.f;
    if (i == 0) d_avglog = 0.f;
}

__global__ __launch_bounds__(256) void k_node_enc(const float* __restrict__ x,
                           const float* __restrict__ w,
                           const float* __restrict__ b) {
    __shared__ float Ws[64*64];
    __shared__ float xs[4][64];
    int t = threadIdx.x;
    for (int i = t; i < 4096; i += 256) Ws[i] = w[i];
    int r = t >> 6, c = t & 63;
    int n = blockIdx.x*4 + r;
    if (n < Nn) xs[r][c] = x[(size_t)n*64 + c];
    __syncthreads();
    if (n < Nn) {
        float s = b[c];
        #pragma unroll
        for (int k = 0; k < 64; k++) s += xs[r][k]*Ws[k*64 + c];
        d_x[(size_t)n*64 + c] = s;
    }
}

__global__ __launch_bounds__(256) void k_deg(const int* __restrict__ dst) {
    int e = blockIdx.x*blockDim.x + threadIdx.x;
    if (e < Ee) atomicAdd(&d_degi[dst[e]], 1);
}

// single-block exclusive scan of degrees -> CSR offsets
__global__ __launch_bounds__(1024) void k_scan() {
    __shared__ int sm[1024];
    int t = threadIdx.x;
    const int CH = (Nn + 1023)/1024;
    int base = t*CH;
    int s = 0;
    for (int i = 0; i < CH; i++) { int idx = base + i; if (idx < Nn) s += d_degi[idx]; }
    sm[t] = s; __syncthreads();
    for (int o = 1; o < 1024; o <<= 1) {
        int v = (t >= o) ? sm[t-o] : 0;
        __syncthreads();
        sm[t] += v;
        __syncthreads();
    }
    int run = sm[t] - s;
    for (int i = 0; i < CH; i++) {
        int idx = base + i;
        if (idx < Nn) { d_off[idx] = run; run += d_degi[idx]; }
    }
    if (t == 1023) d_off[Nn] = sm[1023];
}

__global__ __launch_bounds__(256) void k_sort(const int* __restrict__ src,
                                              const int* __restrict__ dst) {
    int e = blockIdx.x*blockDim.x + threadIdx.x;
    if (e < Ee) {
        int d = dst[e];
        int r = atomicAdd(&d_cursor[d], 1);
        int pos = d_off[d] + r;
        d_srcs[pos]  = src[e];
        d_eperm[pos] = e;
    }
}

__global__ __launch_bounds__(256) void k_ea_enc(const float* __restrict__ ea,
                         const float* __restrict__ w,
                         const float* __restrict__ b) {
    __shared__ float Ws[16*64];
    __shared__ float es[4][16];
    int t = threadIdx.x;
    for (int i = t; i < 1024; i += 256) Ws[i] = w[i];
    int r = t >> 6, c = t & 63;
    int p = blockIdx.x*4 + r;
    if (p < Ee && c < 16) {
        int e = d_eperm[p];
        es[r][c] = ea[(size_t)e*EAD + c];
    }
    __syncthreads();
    if (p < Ee) {
        float s = b[c];
        #pragma unroll
        for (int k = 0; k < 16; k++) s += es[r][k]*Ws[k*64 + c];
        d_ea[(size_t)p*64 + c] = s;
    }
}

__global__ __launch_bounds__(256) void k_avglog() {
    __shared__ float sm[256];
    int t = threadIdx.x; float s = 0.f;
    for (int n = blockIdx.x*256 + t; n < Nn; n += gridDim.x*256)
        s += logf((float)d_degi[n] + 1.f);
    sm[t] = s; __syncthreads();
    for (int o = 128; o > 0; o >>= 1) { if (t < o) sm[t] += sm[t+o]; __syncthreads(); }
    if (t == 0) atomicAdd(&d_avglog, sm[0]);
}

__global__ __launch_bounds__(256) void k_amp() {
    int n = blockIdx.x*blockDim.x + threadIdx.x;
    if (n < Nn) {
        float degc = fmaxf((float)d_degi[n], 1.f);
        float ld = logf(degc + 1.f);
        float avg = d_avglog / (float)Nn;
        d_amp[n] = ld/avg;
        d_att[n] = avg/ld;
    }
}

// ---------------- per-layer kernels ----------------
// dst chunk (dims 0..63) is constant per segment: analytic stats
__global__ __launch_bounds__(256) void k_agg_const() {
    int i = blockIdx.x*blockDim.x + threadIdx.x;
    if (i >= Nn*64) return;
    int n = i >> 6, c = i & 63;
    float xv = d_x[(size_t)n*64 + c];
    int deg = d_degi[n];
    float m = (deg > 0) ? xv : 0.f;
    size_t b = (size_t)n*768 + c;
    d_agg[b]       = m;               // mean
    d_agg[b+192]   = m;               // min
    d_agg[b+384]   = m;               // max
    d_agg[b+576]   = sqrtf(1e-5f);    // std of constant = sqrt(eps)
}

// src + ea chunks (dims 64..191): one block per node, register accumulation
__global__ __launch_bounds__(128) void k_agg_edge() {
    int n = blockIdx.x;
    int t = threadIdx.x;            // 0..127
    int e0 = d_off[n], e1 = d_off[n+1];
    float s = 0.f, ss = 0.f, mx = -3.4e38f, mn = 3.4e38f;
    for (int p = e0; p < e1; p++) {
        float v;
        if (t < 64) {
            int sn = d_srcs[p];
            v = d_x[(size_t)sn*64 + t];
        } else {
            v = d_ea[(size_t)p*64 + (t - 64)];
        }
        s += v; ss += v*v;
        mx = fmaxf(mx, v); mn = fminf(mn, v);
    }
    int deg = e1 - e0;
    float inv = 1.f / fmaxf((float)deg, 1.f);
    float mean = s*inv;
    float msq  = ss*inv;
    float sd   = sqrtf(fmaxf(msq - mean*mean, 0.f) + 1e-5f);
    if (deg == 0) { mx = 0.f; mn = 0.f; }
    size_t b = (size_t)n*768 + 64 + t;
    d_agg[b]     = mean;
    d_agg[b+192] = mn;
    d_agg[b+384] = mx;
    d_agg[b+576] = sd;
}

// C[bm:bm+64, nt*64 : nt*64+64] = agg[bm:,0:768] @ W[l][nt*768:(nt+1)*768, 0:64]
__global__ __launch_bounds__(256) void k_gemm(const float* __restrict__ convw, int l) {
    __shared__ float As[16][65];
    __shared__ float Bs[16][65];
    int tid = threadIdx.x;
    int bm = blockIdx.x*64;
    const float* Bp = convw + ((size_t)l*2304 + (size_t)blockIdx.y*768)*64;
    float acc[4][4] = {};
    int ty = tid >> 4, tx = tid & 15;
    int arow = tid >> 2;
    int akk  = (tid & 3)*4;
    int brow = tid >> 6;
    int bcol = tid & 63;
    for (int k0 = 0; k0 < 768; k0 += 16) {
        #pragma unroll
        for (int i = 0; i < 4; i++) {
            int r = bm + arow;
            float v = (r < Nn) ? d_agg[(size_t)r*768 + k0 + akk + i] : 0.f;
            As[akk + i][arow] = v;
        }
        #pragma unroll
        for (int i = 0; i < 4; i++)
            Bs[brow + i*4][bcol] = Bp[(size_t)(k0 + brow + i*4)*64 + bcol];
        __syncthreads();
        #pragma unroll
        for (int kk = 0; kk < 16; kk++) {
            float a[4], b[4];
            #pragma unroll
            for (int i = 0; i < 4; i++) a[i] = As[kk][ty*4 + i];
            #pragma unroll
            for (int j = 0; j < 4; j++) b[j] = Bs[kk][tx*4 + j];
            #pragma unroll
            for (int i = 0; i < 4; i++)
                #pragma unroll
                for (int j = 0; j < 4; j++)
                    acc[i][j] += a[i]*b[j];
        }
        __syncthreads();
    }
    #pragma unroll
    for (int i = 0; i < 4; i++) {
        int r = bm + ty*4 + i;
        if (r < Nn)
            #pragma unroll
            for (int j = 0; j < 4; j++)
                d_y[(size_t)r*192 + blockIdx.y*64 + tx*4 + j] = acc[i][j];
    }
}

__global__ __launch_bounds__(256) void k_combine(const float* __restrict__ convb, int l) {
    int i = blockIdx.x*blockDim.x + threadIdx.x;
    if (i >= Nn*64) return;
    int n = i >> 6, j = i & 63;
    size_t b = (size_t)n*192;
    float h = d_y[b+j] + d_amp[n]*d_y[b+64+j] + d_att[n]*d_y[b+128+j] + convb[l*64 + j];
    d_h[i] = h;
}

__global__ __launch_bounds__(128) void k_bnzero() {
    int t = threadIdx.x;
    if (t < HID) { d_bnsum[t] = 0.f; d_bnss[t] = 0.f; }
}

__global__ __launch_bounds__(256) void k_bnstat() {
    __shared__ float sm1[256], sm2[256];
    int t = threadIdx.x;
    int col = t & 63, rg = t >> 6;
    float s = 0.f, ss = 0.f;
    for (int r = blockIdx.x*4 + rg; r < Nn; r += gridDim.x*4) {
        float v = d_h[(size_t)r*64 + col];
        s += v; ss += v*v;
    }
    sm1[t] = s; sm2[t] = ss; __syncthreads();
    if (t < 64) {
        float a = sm1[t] + sm1[t+64] + sm1[t+128] + sm1[t+192];
        float c = sm2[t] + sm2[t+64] + sm2[t+128] + sm2[t+192];
        atomicAdd(&d_bnsum[t], a);
        atomicAdd(&d_bnss[t], c);
    }
}

__global__ __launch_bounds__(256) void k_bnapply(const float* __restrict__ g,
                                                 const float* __restrict__ b, int l) {
    int i = blockIdx.x*blockDim.x + threadIdx.x;
    if (i >= Nn*64) return;
    int j = i & 63;
    float mu  = d_bnsum[j] / (float)Nn;
    float var = d_bnss[j] / (float)Nn - mu*mu;
    float h = (d_h[i] - mu) * rsqrtf(var + 1e-5f) * g[l*64 + j] + b[l*64 + j];
    d_x[i] = fmaxf(h, 0.f) + d_x[i];
}

// ---------------- readout ----------------
__global__ __launch_bounds__(256) void k_pool(const int* __restrict__ batch) {
    int i = blockIdx.x*blockDim.x + threadIdx.x;
    if (i >= Nn*64) return;
    int n = i >> 6, j = i & 63;
    int bg = batch[n];
    atomicAdd(&d_pool[bg*64 + j], d_x[i]);
    if (j == 0) atomicAdd(&d_cntg[bg], 1.f);
}

__global__ __launch_bounds__(256) void k_final(const float* __restrict__ f1w,
                        const float* __restrict__ f1b,
                        const float* __restrict__ f2w, const float* __restrict__ f2b,
                        const float* __restrict__ f3w, const float* __restrict__ f3b,
                        float* __restrict__ out) {
    __shared__ float G[64*64], H1[64*32], H2[64*16];
    int t = threadIdx.x;
    for (int i = t; i < 4096; i += 256) {
        int g = i >> 6;
        G[i] = d_pool[i] / fmaxf(d_cntg[g], 1.f);
    }
    __syncthreads();
    for (int i = t; i < 2048; i += 256) {
        int g = i >> 5, o = i & 31;
        float s = f1b[o];
        #pragma unroll
        for (int k = 0; k < 64; k++) s += G[g*64 + k]*f1w[k*32 + o];
        H1[i] = fmaxf(s, 0.f);
    }
    __syncthreads();
    for (int i = t; i < 1024; i += 256) {
        int g = i >> 4, o = i & 15;
        float s = f2b[o];
        #pragma unroll
        for (int k = 0; k < 32; k++) s += H1[g*32 + k]*f2w[k*16 + o];
        H2[i] = fmaxf(s, 0.f);
    }
    __syncthreads();
    for (int i = t; i < 640; i += 256) {
        int g = i/10, o = i%10;
        float s = f3b[o];
        #pragma unroll
        for (int k = 0; k < 16; k++) s += H2[g*16 + k]*f3w[k*10 + o];
        out[i] = s;
    }
}

// ---------------- launch ----------------
extern "C" void kernel_launch(void* const* d_in, const int* in_sizes, int n_in,
                              void* d_out, int out_size) {
    const float* x      = (const float*)d_in[0];
    const int*   ei     = (const int*)  d_in[1];
    const int*   batch  = (const int*)  d_in[2];
    const float* eattr  = (const float*)d_in[3];
    const float* node_w = (const float*)d_in[4];
    const float* node_b = (const float*)d_in[5];
    const float* edge_w = (const float*)d_in[6];
    const float* edge_b = (const float*)d_in[7];
    const float* conv_w = (const float*)d_in[8];
    const float* conv_b = (const float*)d_in[9];
    const float* bn_g   = (const float*)d_in[10];
    const float* bn_b   = (const float*)d_in[11];
    const float* f1w    = (const float*)d_in[12];
    const float* f1b    = (const float*)d_in[13];
    const float* f2w    = (const float*)d_in[14];
    const float* f2b    = (const float*)d_in[15];
    const float* f3w    = (const float*)d_in[16];
    const float* f3b    = (const float*)d_in[17];
    float* out = (float*)d_out;

    const int* src = ei;
    const int* dst = ei + Ee;

    k_zero<<<(Nn + 255)/256, 256>>>();
    k_node_enc<<<(Nn + 3)/4, 256>>>(x, node_w, node_b);
    k_deg<<<(Ee + 255)/256, 256>>>(dst);
    k_scan<<<1, 1024>>>();
    k_sort<<<(Ee + 255)/256, 256>>>(src, dst);
    k_ea_enc<<<(Ee + 3)/4, 256>>>(eattr, edge_w, edge_b);
    k_avglog<<<256, 256>>>();
    k_amp<<<(Nn + 255)/256, 256>>>();

    for (int l = 0; l < NLAY; l++) {
        k_agg_const<<<(Nn*64 + 255)/256, 256>>>();
        k_agg_edge<<<Nn, 128>>>();
        dim3 gg((Nn + 63)/64, 3);
        k_gemm<<<gg, 256>>>(conv_w, l);
        k_combine<<<(Nn*64 + 255)/256, 256>>>(conv_b, l);
        k_bnzero<<<1, 128>>>();
        k_bnstat<<<128, 256>>>();
        k_bnapply<<<(Nn*64 + 255)/256, 256>>>(bn_g, bn_b, l);
    }

    k_pool<<<(Nn*64 + 255)/256, 256>>>(batch);
    k_final<<<1, 256>>>(f1w, f1b, f2w, f2b, f3w, f3b, out);
}

// round 6
// speedup vs baseline: 1.7873x; 1.7873x over previous
#include <cuda_runtime.h>
#include <cuda_bf16.h>
#include <math.h>
#include <stdint.h>

#define Nn 50000
#define Ee 800000
#define HID 64
#define EAD 16
#define NLAY 3
#define NCLS 10
#define NGR 64
#define KTOT 576
#define MTILES ((Nn + 127)/128)

// ---------------- static scratch ----------------
__device__ float d_x[(size_t)Nn*HID];
__device__ float d_ea[(size_t)Ee*HID];
__device__ int   d_srcs[Ee];
__device__ int   d_eperm[Ee];
__device__ int   d_degi[Nn];
__device__ int   d_off[Nn+1];
__device__ int   d_cursor[Nn];
__device__ float d_amp[Nn], d_att[Nn];
__device__ float d_avglog;
__device__ __align__(16) __nv_bfloat16 d_aggH[(size_t)Nn*KTOT];
__device__ __align__(16) __nv_bfloat16 d_aggL[(size_t)Nn*KTOT];
__device__ __align__(16) __nv_bfloat16 d_BH[(size_t)192*KTOT];
__device__ __align__(16) __nv_bfloat16 d_BL[(size_t)192*KTOT];
__device__ float d_cvec[192];
__device__ float d_y[(size_t)Nn*192];
__device__ float d_h[(size_t)Nn*HID];
__device__ float d_bnsum[HID], d_bnss[HID];
__device__ float d_pool[NGR*HID];
__device__ float d_cntg[NGR];

// ---------------- setup kernels ----------------
__global__ __launch_bounds__(256) void k_zero() {
    int i = blockIdx.x*blockDim.x + threadIdx.x;
    if (i < Nn) { d_degi[i] = 0; d_cursor[i] = 0; }
    if (i < NGR*HID) d_pool[i] = 0.f;
    if (i < NGR) d_cntg[i] = 0.f;
    if (i == 0) d_avglog = 0.f;
}

__global__ __launch_bounds__(256) void k_node_enc(const float* __restrict__ x,
                           const float* __restrict__ w, const float* __restrict__ b) {
    __shared__ float Ws[64*64];
    __shared__ float xs[4][64];
    int t = threadIdx.x;
    for (int i = t; i < 4096; i += 256) Ws[i] = w[i];
    int r = t >> 6, c = t & 63;
    int n = blockIdx.x*4 + r;
    if (n < Nn) xs[r][c] = x[(size_t)n*64 + c];
    __syncthreads();
    if (n < Nn) {
        float s = b[c];
        #pragma unroll
        for (int k = 0; k < 64; k++) s += xs[r][k]*Ws[k*64 + c];
        d_x[(size_t)n*64 + c] = s;
    }
}

__global__ __launch_bounds__(256) void k_deg(const int* __restrict__ dst) {
    int e = blockIdx.x*blockDim.x + threadIdx.x;
    if (e < Ee) atomicAdd(&d_degi[dst[e]], 1);
}

__global__ __launch_bounds__(1024) void k_scan() {
    __shared__ int sm[1024];
    int t = threadIdx.x;
    const int CH = (Nn + 1023)/1024;
    int base = t*CH;
    int s = 0;
    for (int i = 0; i < CH; i++) { int idx = base + i; if (idx < Nn) s += d_degi[idx]; }
    sm[t] = s; __syncthreads();
    for (int o = 1; o < 1024; o <<= 1) {
        int v = (t >= o) ? sm[t-o] : 0;
        __syncthreads();
        sm[t] += v;
        __syncthreads();
    }
    int run = sm[t] - s;
    for (int i = 0; i < CH; i++) {
        int idx = base + i;
        if (idx < Nn) { d_off[idx] = run; run += d_degi[idx]; }
    }
    if (t == 1023) d_off[Nn] = sm[1023];
}

__global__ __launch_bounds__(256) void k_sort(const int* __restrict__ src,
                                              const int* __restrict__ dst) {
    int e = blockIdx.x*blockDim.x + threadIdx.x;
    if (e < Ee) {
        int d = dst[e];
        int r = atomicAdd(&d_cursor[d], 1);
        int pos = d_off[d] + r;
        d_srcs[pos]  = src[e];
        d_eperm[pos] = e;
    }
}

__global__ __launch_bounds__(256) void k_ea_enc(const float* __restrict__ ea,
                         const float* __restrict__ w, const float* __restrict__ b) {
    __shared__ float Ws[16*64];
    __shared__ float es[4][16];
    int t = threadIdx.x;
    for (int i = t; i < 1024; i += 256) Ws[i] = w[i];
    int r = t >> 6, c = t & 63;
    int p = blockIdx.x*4 + r;
    if (p < Ee && c < 16) {
        int e = d_eperm[p];
        es[r][c] = ea[(size_t)e*EAD + c];
    }
    __syncthreads();
    if (p < Ee) {
        float s = b[c];
        #pragma unroll
        for (int k = 0; k < 16; k++) s += es[r][k]*Ws[k*64 + c];
        d_ea[(size_t)p*64 + c] = s;
    }
}

__global__ __launch_bounds__(256) void k_avglog() {
    __shared__ float sm[256];
    int t = threadIdx.x; float s = 0.f;
    for (int n = blockIdx.x*256 + t; n < Nn; n += gridDim.x*256)
        s += logf((float)d_degi[n] + 1.f);
    sm[t] = s; __syncthreads();
    for (int o = 128; o > 0; o >>= 1) { if (t < o) sm[t] += sm[t+o]; __syncthreads(); }
    if (t == 0) atomicAdd(&d_avglog, sm[0]);
}

__global__ __launch_bounds__(256) void k_amp() {
    int n = blockIdx.x*blockDim.x + threadIdx.x;
    if (n < Nn) {
        float degc = fmaxf((float)d_degi[n], 1.f);
        float ld = logf(degc + 1.f);
        float avg = d_avglog / (float)Nn;
        d_amp[n] = ld/avg;
        d_att[n] = avg/ld;
    }
}

// ---------------- per-layer kernels ----------------
__device__ __forceinline__ void sthl(size_t idx, float v) {
    __nv_bfloat16 h = __float2bfloat16(v);
    d_aggH[idx] = h;
    d_aggL[idx] = __float2bfloat16(v - __bfloat162float(h));
}

// edge aggregation + fold: A = [mean|mn|mx|std of (src,ea) (512) | masked x (64)]
__global__ __launch_bounds__(128) void k_agg() {
    int n = blockIdx.x;
    int t = threadIdx.x;            // 0..127
    int e0 = d_off[n], e1 = d_off[n+1];
    float s = 0.f, ss = 0.f, mx = -3.4e38f, mn = 3.4e38f;
    for (int p = e0; p < e1; p++) {
        float v;
        if (t < 64) {
            int sn = d_srcs[p];
            v = d_x[(size_t)sn*64 + t];
        } else {
            v = d_ea[(size_t)p*64 + (t - 64)];
        }
        s += v; ss += v*v;
        mx = fmaxf(mx, v); mn = fminf(mn, v);
    }
    int deg = e1 - e0;
    float inv = 1.f / fmaxf((float)deg, 1.f);
    float mean = s*inv;
    float msq  = ss*inv;
    float sd   = sqrtf(fmaxf(msq - mean*mean, 0.f) + 1e-5f);
    if (deg == 0) { mx = 0.f; mn = 0.f; }
    size_t b = (size_t)n*KTOT + t;
    sthl(b,       mean);
    sthl(b + 128, mn);
    sthl(b + 256, mx);
    sthl(b + 384, sd);
    if (t < 64) {
        float m = (deg > 0) ? d_x[(size_t)n*64 + t] : 0.f;
        sthl((size_t)n*KTOT + 512 + t, m);
    }
}

// folded B [192 x 576] bf16 hi/lo (row = output col; layout Bt[n][k]) + cvec
__global__ __launch_bounds__(64) void k_prepB(const float* __restrict__ convw, int l) {
    int c = blockIdx.x;             // 0..191 output column
    int tch = c >> 6, cc = c & 63;
    const float* W = convw + ((size_t)l*2304 + (size_t)tch*768)*64;
    const int LUT[8] = {64,128,256,320,448,512,640,704};
    for (int k = threadIdx.x; k < KTOT; k += 64) {
        float v;
        if (k < 512) {
            v = W[(size_t)(LUT[k >> 6] + (k & 63))*64 + cc];
        } else {
            int r = k - 512;
            v = W[(size_t)r*64 + cc] + W[(size_t)(192 + r)*64 + cc] + W[(size_t)(384 + r)*64 + cc];
        }
        __nv_bfloat16 h = __float2bfloat16(v);
        d_BH[(size_t)c*KTOT + k] = h;
        d_BL[(size_t)c*KTOT + k] = __float2bfloat16(v - __bfloat162float(h));
    }
    if (threadIdx.x == 0) {
        float s = 0.f;
        for (int r = 0; r < 64; r++) s += W[(size_t)(576 + r)*64 + cc];
        d_cvec[c] = 0.0031622776601683794f * s;   // sqrt(1e-5) * sum(W_std_dst)
    }
}

// ------------- warp-mma bf16 GEMM: d_y[128 tile, 192] += A@B (3 hi/lo combos) -------------
#define ASTR 40                       // smem row stride in halves (conflict-free)
#define SMA_HALVES (128*ASTR)         // 5120
#define SMB_HALVES (192*ASTR)         // 7680
#define BUF_HALVES (SMA_HALVES + SMB_HALVES)   // 12800
#define SMEM_GEMM (2*BUF_HALVES*2)    // bytes = 51200

__global__ __launch_bounds__(256) void k_gemm_mma() {
    extern __shared__ __nv_bfloat16 smg[];
    int t = threadIdx.x;
    int lane = t & 31, warp = t >> 5;
    int warpM = warp & 3, warpN = warp >> 2;     // 4 x 2 warp grid
    int bm = blockIdx.x * 128;
    int g = lane >> 2, tg = lane & 3;

    float c[2][12][4];
    #pragma unroll
    for (int m = 0; m < 2; m++)
        #pragma unroll
        for (int j = 0; j < 12; j++)
            #pragma unroll
            for (int q = 0; q < 4; q++) c[m][j][q] = 0.f;

    // gmem->reg staging indices
    int arow = t >> 1, akoff = (t & 1) * 16;     // A: 128 rows x 32 halves
    uint4 ra0, ra1, rb0, rb1, rb2;

    const int NIT = 54;                          // 3 combos x 18 chunks
    // prefetch iteration 0
    {
        const __nv_bfloat16* As = d_aggH;
        const __nv_bfloat16* Bs = d_BH;
        int grow = bm + arow;
        if (grow < Nn) {
            const __nv_bfloat16* p = As + (size_t)grow*KTOT + akoff;
            ra0 = *(const uint4*)p; ra1 = *(const uint4*)(p + 8);
        } else { ra0 = make_uint4(0,0,0,0); ra1 = ra0; }
        int u0 = t, u1 = t + 256, u2 = t + 512;
        rb0 = *(const uint4*)(Bs + (size_t)(u0>>2)*KTOT + (u0&3)*8);
        rb1 = *(const uint4*)(Bs + (size_t)(u1>>2)*KTOT + (u1&3)*8);
        rb2 = *(const uint4*)(Bs + (size_t)(u2>>2)*KTOT + (u2&3)*8);
    }

    for (int it = 0; it < NIT; it++) {
        __nv_bfloat16* buf  = smg + (it & 1)*BUF_HALVES;
        __nv_bfloat16* abuf = buf;
        __nv_bfloat16* bbuf = buf + SMA_HALVES;
        // store staged regs
        *(uint4*)(abuf + arow*ASTR + akoff)     = ra0;
        *(uint4*)(abuf + arow*ASTR + akoff + 8) = ra1;
        {
            int u0 = t, u1 = t + 256, u2 = t + 512;
            *(uint4*)(bbuf + (u0>>2)*ASTR + (u0&3)*8) = rb0;
            *(uint4*)(bbuf + (u1>>2)*ASTR + (u1&3)*8) = rb1;
            *(uint4*)(bbuf + (u2>>2)*ASTR + (u2&3)*8) = rb2;
        }
        __syncthreads();
        // prefetch next iteration
        if (it + 1 < NIT) {
            int nit = it + 1;
            int combo = nit / 18, kc = nit % 18, k0 = kc * 32;
            const __nv_bfloat16* As = (combo == 2) ? d_aggL : d_aggH;
            const __nv_bfloat16* Bs = (combo == 1) ? d_BL   : d_BH;
            int grow = bm + arow;
            if (grow < Nn) {
                const __nv_bfloat16* p = As + (size_t)grow*KTOT + k0 + akoff;
                ra0 = *(const uint4*)p; ra1 = *(const uint4*)(p + 8);
            } else { ra0 = make_uint4(0,0,0,0); ra1 = ra0; }
            int u0 = t, u1 = t + 256, u2 = t + 512;
            rb0 = *(const uint4*)(Bs + (size_t)(u0>>2)*KTOT + k0 + (u0&3)*8);
            rb1 = *(const uint4*)(Bs + (size_t)(u1>>2)*KTOT + k0 + (u1&3)*8);
            rb2 = *(const uint4*)(Bs + (size_t)(u2>>2)*KTOT + k0 + (u2&3)*8);
        }
        // compute on current buffer: 2 k-steps of 16
        #pragma unroll
        for (int ks = 0; ks < 2; ks++) {
            uint32_t a[2][4];
            #pragma unroll
            for (int m = 0; m < 2; m++) {
                int r0 = warpM*32 + m*16;
                const __nv_bfloat16* p0 = abuf + (r0 + g)*ASTR + ks*16 + tg*2;
                const __nv_bfloat16* p1 = abuf + (r0 + g + 8)*ASTR + ks*16 + tg*2;
                a[m][0] = *(const uint32_t*)p0;
                a[m][1] = *(const uint32_t*)p1;
                a[m][2] = *(const uint32_t*)(p0 + 8);
                a[m][3] = *(const uint32_t*)(p1 + 8);
            }
            #pragma unroll
            for (int j = 0; j < 12; j++) {
                int n0 = warpN*96 + j*8 + g;
                const __nv_bfloat16* pb = bbuf + n0*ASTR + ks*16 + tg*2;
                uint32_t b0 = *(const uint32_t*)pb;
                uint32_t b1 = *(const uint32_t*)(pb + 8);
                #pragma unroll
                for (int m = 0; m < 2; m++) {
                    asm volatile(
                        "mma.sync.aligned.m16n8k16.row.col.f32.bf16.bf16.f32 "
                        "{%0,%1,%2,%3}, {%4,%5,%6,%7}, {%8,%9}, {%0,%1,%2,%3};"
                        : "+f"(c[m][j][0]), "+f"(c[m][j][1]),
                          "+f"(c[m][j][2]), "+f"(c[m][j][3])
                        : "r"(a[m][0]), "r"(a[m][1]), "r"(a[m][2]), "r"(a[m][3]),
                          "r"(b0), "r"(b1));
                }
            }
        }
        __syncthreads();
    }

    // epilogue: write C to d_y
    #pragma unroll
    for (int m = 0; m < 2; m++) {
        int r0 = bm + warpM*32 + m*16 + g;
        #pragma unroll
        for (int j = 0; j < 12; j++) {
            int col = warpN*96 + j*8 + tg*2;
            if (r0 < Nn) {
                d_y[(size_t)r0*192 + col]     = c[m][j][0];
                d_y[(size_t)r0*192 + col + 1] = c[m][j][1];
            }
            if (r0 + 8 < Nn) {
                d_y[(size_t)(r0+8)*192 + col]     = c[m][j][2];
                d_y[(size_t)(r0+8)*192 + col + 1] = c[m][j][3];
            }
        }
    }
}

__global__ __launch_bounds__(256) void k_combine(const float* __restrict__ convb, int l) {
    int i = blockIdx.x*blockDim.x + threadIdx.x;
    if (i >= Nn*64) return;
    int n = i >> 6, j = i & 63;
    size_t b = (size_t)n*192;
    float y0 = d_y[b + j]       + d_cvec[j];
    float y1 = d_y[b + 64 + j]  + d_cvec[64 + j];
    float y2 = d_y[b + 128 + j] + d_cvec[128 + j];
    d_h[i] = y0 + d_amp[n]*y1 + d_att[n]*y2 + convb[l*64 + j];
}

__global__ __launch_bounds__(128) void k_bnzero() {
    int t = threadIdx.x;
    if (t < HID) { d_bnsum[t] = 0.f; d_bnss[t] = 0.f; }
}

__global__ __launch_bounds__(256) void k_bnstat() {
    __shared__ float sm1[256], sm2[256];
    int t = threadIdx.x;
    int col = t & 63, rg = t >> 6;
    float s = 0.f, ss = 0.f;
    for (int r = blockIdx.x*4 + rg; r < Nn; r += gridDim.x*4) {
        float v = d_h[(size_t)r*64 + col];
        s += v; ss += v*v;
    }
    sm1[t] = s; sm2[t] = ss; __syncthreads();
    if (t < 64) {
        float a = sm1[t] + sm1[t+64] + sm1[t+128] + sm1[t+192];
        float c = sm2[t] + sm2[t+64] + sm2[t+128] + sm2[t+192];
        atomicAdd(&d_bnsum[t], a);
        atomicAdd(&d_bnss[t], c);
    }
}

__global__ __launch_bounds__(256) void k_bnapply(const float* __restrict__ g,
                                                 const float* __restrict__ b, int l) {
    int i = blockIdx.x*blockDim.x + threadIdx.x;
    if (i >= Nn*64) return;
    int j = i & 63;
    float mu  = d_bnsum[j] / (float)Nn;
    float var = d_bnss[j] / (float)Nn - mu*mu;
    float h = (d_h[i] - mu) * rsqrtf(var + 1e-5f) * g[l*64 + j] + b[l*64 + j];
    d_x[i] = fmaxf(h, 0.f) + d_x[i];
}

// ---------------- readout ----------------
__global__ __launch_bounds__(256) void k_pool(const int* __restrict__ batch) {
    int i = blockIdx.x*blockDim.x + threadIdx.x;
    if (i >= Nn*64) return;
    int n = i >> 6, j = i & 63;
    int bg = batch[n];
    atomicAdd(&d_pool[bg*64 + j], d_x[i]);
    if (j == 0) atomicAdd(&d_cntg[bg], 1.f);
}

__global__ __launch_bounds__(256) void k_final(const float* __restrict__ f1w,
                        const float* __restrict__ f1b,
                        const float* __restrict__ f2w, const float* __restrict__ f2b,
                        const float* __restrict__ f3w, const float* __restrict__ f3b,
                        float* __restrict__ out) {
    __shared__ float G[64*64], H1[64*32], H2[64*16];
    int t = threadIdx.x;
    for (int i = t; i < 4096; i += 256) {
        int g = i >> 6;
        G[i] = d_pool[i] / fmaxf(d_cntg[g], 1.f);
    }
    __syncthreads();
    for (int i = t; i < 2048; i += 256) {
        int g = i >> 5, o = i & 31;
        float s = f1b[o];
        #pragma unroll
        for (int k = 0; k < 64; k++) s += G[g*64 + k]*f1w[k*32 + o];
        H1[i] = fmaxf(s, 0.f);
    }
    __syncthreads();
    for (int i = t; i < 1024; i += 256) {
        int g = i >> 4, o = i & 15;
        float s = f2b[o];
        #pragma unroll
        for (int k = 0; k < 32; k++) s += H1[g*32 + k]*f2w[k*16 + o];
        H2[i] = fmaxf(s, 0.f);
    }
    __syncthreads();
    for (int i = t; i < 640; i += 256) {
        int g = i/10, o = i%10;
        float s = f3b[o];
        #pragma unroll
        for (int k = 0; k < 16; k++) s += H2[g*16 + k]*f3w[k*10 + o];
        out[i] = s;
    }
}

// ---------------- launch ----------------
extern "C" void kernel_launch(void* const* d_in, const int* in_sizes, int n_in,
                              void* d_out, int out_size) {
    const float* x      = (const float*)d_in[0];
    const int*   ei     = (const int*)  d_in[1];
    const int*   batch  = (const int*)  d_in[2];
    const float* eattr  = (const float*)d_in[3];
    const float* node_w = (const float*)d_in[4];
    const float* node_b = (const float*)d_in[5];
    const float* edge_w = (const float*)d_in[6];
    const float* edge_b = (const float*)d_in[7];
    const float* conv_w = (const float*)d_in[8];
    const float* conv_b = (const float*)d_in[9];
    const float* bn_g   = (const float*)d_in[10];
    const float* bn_b   = (const float*)d_in[11];
    const float* f1w    = (const float*)d_in[12];
    const float* f1b    = (const float*)d_in[13];
    const float* f2w    = (const float*)d_in[14];
    const float* f2b    = (const float*)d_in[15];
    const float* f3w    = (const float*)d_in[16];
    const float* f3b    = (const float*)d_in[17];
    float* out = (float*)d_out;

    const int* src = ei;
    const int* dst = ei + Ee;

    static int smset = 0;
    if (!smset) {
        cudaFuncSetAttribute(k_gemm_mma, cudaFuncAttributeMaxDynamicSharedMemorySize, SMEM_GEMM);
        smset = 1;
    }

    k_zero<<<(Nn + 255)/256, 256>>>();
    k_node_enc<<<(Nn + 3)/4, 256>>>(x, node_w, node_b);
    k_deg<<<(Ee + 255)/256, 256>>>(dst);
    k_scan<<<1, 1024>>>();
    k_sort<<<(Ee + 255)/256, 256>>>(src, dst);
    k_ea_enc<<<(Ee + 3)/4, 256>>>(eattr, edge_w, edge_b);
    k_avglog<<<256, 256>>>();
    k_amp<<<(Nn + 255)/256, 256>>>();

    for (int l = 0; l < NLAY; l++) {
        k_agg<<<Nn, 128>>>();
        k_prepB<<<192, 64>>>(conv_w, l);
        k_gemm_mma<<<MTILES, 256, SMEM_GEMM>>>();
        k_combine<<<(Nn*64 + 255)/256, 256>>>(conv_b, l);
        k_bnzero<<<1, 128>>>();
        k_bnstat<<<128, 256>>>();
        k_bnapply<<<(Nn*64 + 255)/256, 256>>>(bn_g, bn_b, l);
    }

    k_pool<<<(Nn*64 + 255)/256, 256>>>(batch);
    k_final<<<1, 256>>>(f1w, f1b, f2w, f2b, f3w, f3b, out);
}